// round 11
// baseline (speedup 1.0000x reference)
#include <cuda_runtime.h>
#include <cuda_bf16.h>
#include <cstdint>

#define EMBED 768
#define OUTD  1024
#define HEADS 8
#define HD    128
#define MAXN  10000
#define MAXE  160000
#define MAXET (MAXN + MAXE)
#define PADN  10112            // 79 * 128

// ---------------- scratch ----------------
__device__ float    g_xs[MAXN * OUTD];
__device__ float    g_h[MAXN * OUTD];        // only rows text/image are written
__device__ float    g_asrc[MAXN * HEADS];
__device__ float    g_adst[MAXN * HEADS];
__device__ float    g_edge[MAXET * HEADS];
__device__ float    g_scal[16];              // [0]=sum(ea), [1..8]=k[h]
__device__ float    g_pool[OUTD];
// CSR by dst
__device__ int      g_deg[MAXN];
__device__ int      g_off[MAXN + 1];
__device__ int      g_cur[MAXN];
__device__ unsigned g_csr[MAXET];            // (edge_id << 14) | src
// bf16-split W^T for tensor-core GEMM
__device__ __nv_bfloat16 g_Whi[(size_t)OUTD * EMBED];   // W^T [n][k]
__device__ __nv_bfloat16 g_Wlo[(size_t)OUTD * EMBED];

// ---------------- PTX helpers ----------------
__device__ __forceinline__ uint32_t smem_u32(const void* p) {
    uint32_t a;
    asm("{ .reg .u64 t; cvta.to.shared.u64 t, %1; cvt.u32.u64 %0, t; }" : "=r"(a) : "l"(p));
    return a;
}
__device__ __forceinline__ void cp16(uint32_t s, const void* g) {
    asm volatile("cp.async.cg.shared.global [%0], [%1], 16;" :: "r"(s), "l"(g));
}
__device__ __forceinline__ void cp_commit() {
    asm volatile("cp.async.commit_group;" ::: "memory");
}
template <int N>
__device__ __forceinline__ void cp_wait() {
    asm volatile("cp.async.wait_group %0;" :: "n"(N) : "memory");
}
__device__ __forceinline__ void ldsm4(uint32_t& r0, uint32_t& r1, uint32_t& r2, uint32_t& r3,
                                      uint32_t addr) {
    asm volatile("ldmatrix.sync.aligned.m8n8.x4.shared.b16 {%0,%1,%2,%3}, [%4];"
                 : "=r"(r0), "=r"(r1), "=r"(r2), "=r"(r3) : "r"(addr));
}
__device__ __forceinline__ void mma16816(float* d, const uint32_t* a, const uint32_t* b) {
    asm volatile(
        "mma.sync.aligned.m16n8k16.row.col.f32.bf16.bf16.f32 "
        "{%0,%1,%2,%3}, {%4,%5,%6,%7}, {%8,%9}, {%0,%1,%2,%3};"
        : "+f"(d[0]), "+f"(d[1]), "+f"(d[2]), "+f"(d[3])
        : "r"(a[0]), "r"(a[1]), "r"(a[2]), "r"(a[3]), "r"(b[0]), "r"(b[1]));
}

__device__ __forceinline__ uint32_t sw_off(int row, int c) {
    return (uint32_t)(row * 64 + ((c ^ ((row >> 1) & 3)) << 4));
}

// ---------------- K0b: W^T split via smem tile transpose (coalesced both ways) ----------------
__global__ __launch_bounds__(256)
void k_cvtW(const float* __restrict__ W) {
    __shared__ float tile[32][33];
    const int k0 = blockIdx.y * 32;
    const int n0 = blockIdx.x * 32;
    const int tx = threadIdx.x & 31, ty = threadIdx.x >> 5;
    #pragma unroll
    for (int i = 0; i < 32; i += 8)
        tile[ty + i][tx] = W[(size_t)(k0 + ty + i) * OUTD + n0 + tx];
    __syncthreads();
    #pragma unroll
    for (int i = 0; i < 32; i += 8) {
        float v = tile[tx][ty + i];
        __nv_bfloat16 hi = __float2bfloat16(v);
        __nv_bfloat16 lo = __float2bfloat16(v - __bfloat162float(hi));
        g_Whi[(size_t)(n0 + ty + i) * EMBED + k0 + tx] = hi;
        g_Wlo[(size_t)(n0 + ty + i) * EMBED + k0 + tx] = lo;
    }
}

// ---------------- K2: HMMA bf16-split GEMM, in-kernel A conversion, fused logits ----------------
#define KCH    32
#define NCHUNK (EMBED / KCH)      // 24
#define TILEB  (128 * 64)         // 8 KB
#define STAGEB (4 * TILEB)        // Ahi, Alo, Bhi, Blo = 32 KB
#define NSTAGE 3
#define SMEM_GEMM (NSTAGE * STAGEB)

__global__ __launch_bounds__(256, 2)
void k_gemm_mma(int M, const float* __restrict__ x,
                const float* __restrict__ att_src,
                const float* __restrict__ att_dst) {
    extern __shared__ char smem[];
    const uint32_t sb = smem_u32(smem);
    const int tid = threadIdx.x;
    const int wid = tid >> 5, lane = tid & 31;
    const int warp_m = wid & 3;
    const int warp_n = wid >> 2;
    const int rowBase = blockIdx.y * 128;
    const int colBase = blockIdx.x * 128;
    const int head = colBase >> 7;

    const __nv_bfloat16* srcB[2] = {
        g_Whi + (size_t)colBase * EMBED,
        g_Wlo + (size_t)colBase * EMBED };

    // per-thread tile slots: 2 chunks of 16B (8 bf16) each
    const int chunk0 = tid * 2;
    const int row0 = chunk0 >> 2, cc0 = chunk0 & 3;
    const int row1 = (chunk0 + 1) >> 2, cc1 = (chunk0 + 1) & 3;
    const uint32_t so0 = sw_off(row0, cc0);
    const uint32_t so1 = sw_off(row1, cc1);
    const int rowg0 = rowBase + row0, rowg1 = rowBase + row1;
    const float4* xv = (const float4*)x;

    // A prefetch registers: 16 floats (8 per chunk)
    float af[16];

    auto ldA = [&](int c) {
        int kb = c * 8;   // float4 index of k0 within a row
        if (rowg0 < M) {
            *(float4*)&af[0] = xv[(size_t)rowg0 * (EMBED / 4) + kb + cc0 * 2];
            *(float4*)&af[4] = xv[(size_t)rowg0 * (EMBED / 4) + kb + cc0 * 2 + 1];
        } else {
            #pragma unroll
            for (int j = 0; j < 8; j++) af[j] = 0.f;
        }
        if (rowg1 < M) {
            *(float4*)&af[8]  = xv[(size_t)rowg1 * (EMBED / 4) + kb + cc1 * 2];
            *(float4*)&af[12] = xv[(size_t)rowg1 * (EMBED / 4) + kb + cc1 * 2 + 1];
        } else {
            #pragma unroll
            for (int j = 8; j < 16; j++) af[j] = 0.f;
        }
    };

    auto stsA = [&](int s) {
        const uint32_t stOff = (uint32_t)(s * STAGEB);
        #pragma unroll
        for (int ch = 0; ch < 2; ch++) {
            const float* f = &af[ch * 8];
            __nv_bfloat162 H[4], L[4];
            #pragma unroll
            for (int j = 0; j < 4; j++) {
                float2 p = make_float2(f[2 * j], f[2 * j + 1]);
                __nv_bfloat162 h = __float22bfloat162_rn(p);
                H[j] = h;
                float2 r = make_float2(p.x - __bfloat162float(h.x),
                                       p.y - __bfloat162float(h.y));
                L[j] = __float22bfloat162_rn(r);
            }
            uint32_t off = (ch == 0) ? so0 : so1;
            *(uint4*)(smem + stOff + off)         = *(uint4*)H;   // Ahi tile 0
            *(uint4*)(smem + stOff + TILEB + off) = *(uint4*)L;   // Alo tile 1
        }
    };

    auto cpB = [&](int c, int s) {
        const uint32_t base = sb + s * STAGEB;
        const int k0 = c * KCH;
        #pragma unroll
        for (int t = 0; t < 2; t++) {
            const __nv_bfloat16* g = srcB[t] + k0;
            cp16(base + (2 + t) * TILEB + so0, g + (size_t)row0 * EMBED + cc0 * 8);
            cp16(base + (2 + t) * TILEB + so1, g + (size_t)row1 * EMBED + cc1 * 8);
        }
        cp_commit();
    };

    // prologue
    ldA(0);
    cpB(0, 0);
    cpB(1, 1);

    float acc[2][8][4];
    #pragma unroll
    for (int mb = 0; mb < 2; mb++)
        #pragma unroll
        for (int nb = 0; nb < 8; nb++)
            #pragma unroll
            for (int j = 0; j < 4; j++) acc[mb][nb][j] = 0.f;

    const int l_tile = lane >> 3, l_rin = lane & 7;

    for (int c = 0; c < NCHUNK; c++) {
        const int s = c % NSTAGE;
        stsA(s);                                   // A(c) from regs -> smem
        if (c + 1 < NCHUNK) cp_wait<1>(); else cp_wait<0>();
        __syncthreads();                           // A stores + B arrival visible
        if (c + 1 < NCHUNK) ldA(c + 1);            // prefetch next A (latency hides under mma)
        if (c + 2 < NCHUNK) cpB(c + 2, (c + 2) % NSTAGE);

        const uint32_t base = sb + s * STAGEB;
        #pragma unroll
        for (int ks = 0; ks < 2; ks++) {
            uint32_t a[2][2][4];
            uint32_t b[2][8][2];
            #pragma unroll
            for (int v = 0; v < 2; v++)
                #pragma unroll
                for (int mb = 0; mb < 2; mb++) {
                    int r = warp_m * 32 + mb * 16 + ((l_tile & 1) << 3) + l_rin;
                    int cch = ks * 2 + (l_tile >> 1);
                    ldsm4(a[v][mb][0], a[v][mb][1], a[v][mb][2], a[v][mb][3],
                          base + v * TILEB + sw_off(r, cch));
                }
            #pragma unroll
            for (int v = 0; v < 2; v++)
                #pragma unroll
                for (int p = 0; p < 4; p++) {
                    int r = warp_n * 64 + p * 16 + ((l_tile >> 1) << 3) + l_rin;
                    int cch = ks * 2 + (l_tile & 1);
                    ldsm4(b[v][p * 2][0], b[v][p * 2][1],
                          b[v][p * 2 + 1][0], b[v][p * 2 + 1][1],
                          base + (2 + v) * TILEB + sw_off(r, cch));
                }
            #pragma unroll
            for (int mb = 0; mb < 2; mb++)
                #pragma unroll
                for (int nb = 0; nb < 8; nb++) {
                    mma16816(acc[mb][nb], a[0][mb], b[0][nb]);
                    mma16816(acc[mb][nb], a[0][mb], b[1][nb]);
                    mma16816(acc[mb][nb], a[1][mb], b[0][nb]);
                }
        }
        // no trailing sync: stage reuse is ordered by the next iteration's sync
    }

    // ---- epilogue: logits via smem (this CTA exclusively owns (row,head)) ----
    __syncthreads();                       // mainloop smem reads done; reuse smem
    float* sasrc = (float*)smem;           // [128]
    float* sadst = sasrc + 128;            // [128]
    ((float*)smem)[tid] = 0.f;             // zero 256 floats
    __syncthreads();

    const int tr = lane >> 2, tc = (lane & 3) * 2;

    float as[16], ad[16];
    #pragma unroll
    for (int nb = 0; nb < 8; nb++)
        #pragma unroll
        for (int j = 0; j < 2; j++) {
            int col = warp_n * 64 + nb * 8 + tc + j;
            as[nb * 2 + j] = att_src[head * HD + col];
            ad[nb * 2 + j] = att_dst[head * HD + col];
        }

    #pragma unroll
    for (int mb = 0; mb < 2; mb++) {
        #pragma unroll
        for (int half = 0; half < 2; half++) {
            int rloc = warp_m * 32 + mb * 16 + half * 8 + tr;
            int row = rowBase + rloc;
            float ps = 0.f, pd = 0.f;
            #pragma unroll
            for (int nb = 0; nb < 8; nb++)
                #pragma unroll
                for (int j = 0; j < 2; j++) {
                    float v = acc[mb][nb][half * 2 + j];
                    ps += v * as[nb * 2 + j];
                    pd += v * ad[nb * 2 + j];
                }
            #pragma unroll
            for (int o = 1; o < 4; o <<= 1) {
                ps += __shfl_xor_sync(0xffffffffu, ps, o);
                pd += __shfl_xor_sync(0xffffffffu, pd, o);
            }
            if (row < M) {
                if ((lane & 3) == 0) {
                    atomicAdd(&sasrc[rloc], ps);
                    atomicAdd(&sadst[rloc], pd);
                }
                float* dst = &g_xs[(size_t)row * OUTD + colBase + warp_n * 64 + tc];
                #pragma unroll
                for (int nb = 0; nb < 8; nb++) {
                    float2 v = make_float2(acc[mb][nb][half * 2], acc[mb][nb][half * 2 + 1]);
                    *(float2*)(dst + nb * 8) = v;
                }
            }
        }
    }
    __syncthreads();
    if (tid < 128) {
        int row = rowBase + tid;
        if (row < M) {
            g_asrc[row * HEADS + head] = sasrc[tid];
            g_adst[row * HEADS + head] = sadst[tid];
        }
    }
}

// ---------------- K1a: parallel sum of ea ----------------
__global__ void k_easum(const float* __restrict__ ea, int E) {
    __shared__ float sh[256];
    float s = 0.f;
    for (int i = blockIdx.x * 256 + threadIdx.x; i < E; i += gridDim.x * 256) s += ea[i];
    sh[threadIdx.x] = s; __syncthreads();
    for (int o = 128; o; o >>= 1) {
        if (threadIdx.x < o) sh[threadIdx.x] += sh[threadIdx.x + o];
        __syncthreads();
    }
    if (threadIdx.x == 0) atomicAdd(&g_scal[0], sh[0]);
}

// ---------------- K1b: per-head edge coefficient k[h] ----------------
__global__ void k_kcoef(const float* __restrict__ Wedge,
                        const float* __restrict__ att_edge) {
    int wid = threadIdx.x >> 5, lane = threadIdx.x & 31;
    float s = 0.f;
    for (int c = lane; c < HD; c += 32)
        s += Wedge[wid * HD + c] * att_edge[wid * HD + c];
    #pragma unroll
    for (int o = 16; o; o >>= 1) s += __shfl_down_sync(0xffffffffu, s, o);
    if (lane == 0) g_scal[1 + wid] = s;
}

// ---------------- CSR build ----------------
__global__ void k_count(const int* __restrict__ ei, int E) {
    int e = blockIdx.x * blockDim.x + threadIdx.x;
    if (e < E) atomicAdd(&g_deg[ei[E + e]], 1);
}

__global__ __launch_bounds__(1024)
void k_scan(int N) {
    __shared__ int sh[1024];
    int t = threadIdx.x;
    int chunk = (N + 1023) / 1024;
    int s0 = min(t * chunk, N), s1 = min(s0 + chunk, N);
    int sum = 0;
    for (int n = s0; n < s1; n++) sum += g_deg[n] + 1;
    sh[t] = sum; __syncthreads();
    for (int o = 1; o < 1024; o <<= 1) {
        int v = (t >= o) ? sh[t - o] : 0;
        __syncthreads();
        sh[t] += v;
        __syncthreads();
    }
    int run = (t == 0) ? 0 : sh[t - 1];
    for (int n = s0; n < s1; n++) {
        g_off[n] = run;
        g_cur[n] = run;
        run += g_deg[n] + 1;
    }
    if (t == 1023) g_off[N] = sh[1023];
}

__global__ void k_fill(const int* __restrict__ ei, int E, int N) {
    int t = blockIdx.x * blockDim.x + threadIdx.x;
    if (t >= E + N) return;
    int d, s;
    if (t < E) { d = ei[E + t]; s = ei[t]; }
    else       { d = s = t - E; }
    int pos = atomicAdd(&g_cur[d], 1);
    g_csr[pos] = ((unsigned)t << 14) | (unsigned)s;
}

// ---------------- K4: fused alpha+exp (denom computed in agg) ----------------
__global__ void k_alphaexp(const int* __restrict__ ei, const float* __restrict__ ea,
                           int E, int N) {
    int t = blockIdx.x * blockDim.x + threadIdx.x;
    int total = (E + N) * HEADS;
    if (t >= total) return;
    int e = t >> 3, h = t & 7;
    int s, d; float av;
    if (e < E) { s = ei[e]; d = ei[E + e]; av = ea[e]; }
    else       { s = d = e - E;            av = g_scal[0] / (float)E; }
    float a = g_asrc[s * HEADS + h] + g_adst[d * HEADS + h] + av * g_scal[1 + h];
    a = (a >= 0.f) ? a : 0.2f * a;
    g_edge[t] = __expf(a);
}

// ---------------- K6: CSR agg + in-warp denom + fused mean-pool ----------------
__global__ __launch_bounds__(256)
void k_agg(int N, const int* __restrict__ tip, const int* __restrict__ iip) {
    __shared__ float spool[OUTD];
    const int tid = threadIdx.x;
    for (int j = tid; j < OUTD; j += 256) spool[j] = 0.f;
    __syncthreads();

    int gw = (blockIdx.x * 256 + tid) >> 5;
    int lane = tid & 31;
    if (gw < N) {
        const int st = g_off[gw], en = g_off[gw + 1];

        float4 acc[HEADS];
        float dsum[HEADS];
        #pragma unroll
        for (int h = 0; h < HEADS; h++) {
            acc[h] = make_float4(0.f, 0.f, 0.f, 0.f);
            dsum[h] = 0.f;
        }

        #pragma unroll 2
        for (int i = st; i < en; i++) {
            unsigned p = g_csr[i];
            int e = p >> 14, s = p & 0x3FFF;
            const float4* row = (const float4*)&g_xs[(size_t)s * OUTD];
            const float* we = &g_edge[(size_t)e * HEADS];
            #pragma unroll
            for (int h = 0; h < HEADS; h++) {
                float w = we[h];
                float4 v = row[h * 32 + lane];
                dsum[h] += w;
                acc[h].x += w * v.x;
                acc[h].y += w * v.y;
                acc[h].z += w * v.z;
                acc[h].w += w * v.w;
            }
        }
        #pragma unroll
        for (int h = 0; h < HEADS; h++) {
            float inv = 1.f / dsum[h];
            acc[h].x *= inv; acc[h].y *= inv; acc[h].z *= inv; acc[h].w *= inv;
        }

        #pragma unroll
        for (int h = 0; h < HEADS; h++) {
            float* sp = &spool[h * HD + lane * 4];
            atomicAdd(sp + 0, acc[h].x);
            atomicAdd(sp + 1, acc[h].y);
            atomicAdd(sp + 2, acc[h].z);
            atomicAdd(sp + 3, acc[h].w);
        }

        int t = tip[0], im = iip[0];
        if (gw == t || gw == im) {
            float4* out = (float4*)&g_h[(size_t)gw * OUTD];
            #pragma unroll
            for (int h = 0; h < HEADS; h++) out[h * 32 + lane] = acc[h];
        }
    }
    __syncthreads();
    for (int j = tid; j < OUTD; j += 256) atomicAdd(&g_pool[j], spool[j]);
}

// ---------------- K8: fused vector + classifier ----------------
__global__ void k_clf(const float* __restrict__ bias,
                      const int* __restrict__ tip, const int* __restrict__ iip,
                      const float* __restrict__ clfW, const float* __restrict__ clfb,
                      int N, float* __restrict__ out) {
    __shared__ float s0[256], s1[256];
    int t = threadIdx.x;
    int ti = tip[0], im = iip[0];
    float a0 = 0.f, a1 = 0.f;
    for (int j = t; j < 3 * OUTD; j += 256) {
        int jj = j & (OUTD - 1);
        int seg = j >> 10;
        float b = bias[jj];
        float f;
        if (seg == 0)      f = g_pool[jj] / (float)N + b;
        else if (seg == 1) f = g_h[(size_t)ti * OUTD + jj] + b;
        else               f = g_h[(size_t)im * OUTD + jj] + b;
        a0 += f * clfW[2 * j];
        a1 += f * clfW[2 * j + 1];
    }
    s0[t] = a0; s1[t] = a1; __syncthreads();
    for (int o = 128; o; o >>= 1) {
        if (t < o) { s0[t] += s0[t + o]; s1[t] += s1[t + o]; }
        __syncthreads();
    }
    if (t == 0) {
        out[0] = s0[0] + clfb[0];
        out[1] = s1[0] + clfb[1];
    }
}

// ---------------- launch ----------------
extern "C" void kernel_launch(void* const* d_in, const int* in_sizes, int n_in,
                              void* d_out, int out_size) {
    const float* x        = (const float*)d_in[0];
    const int*   ei       = (const int*)  d_in[1];
    const float* ea       = (const float*)d_in[2];
    const int*   tip      = (const int*)  d_in[3];
    const int*   iip      = (const int*)  d_in[4];
    const float* W        = (const float*)d_in[5];
    const float* att_src  = (const float*)d_in[6];
    const float* att_dst  = (const float*)d_in[7];
    const float* Wedge    = (const float*)d_in[8];
    const float* att_edge = (const float*)d_in[9];
    const float* bias     = (const float*)d_in[10];
    const float* clfW     = (const float*)d_in[11];
    const float* clfb     = (const float*)d_in[12];
    float* out = (float*)d_out;

    int N  = in_sizes[0] / EMBED;
    int E  = in_sizes[1] / 2;
    int ET = E + N;

    static cudaStream_t s1, s2;
    static cudaEvent_t evFork, evCSR, evW;
    static int inited = 0;
    if (!inited) {
        cudaStreamCreateWithFlags(&s1, cudaStreamNonBlocking);
        cudaStreamCreateWithFlags(&s2, cudaStreamNonBlocking);
        cudaEventCreateWithFlags(&evFork, cudaEventDisableTiming);
        cudaEventCreateWithFlags(&evCSR,  cudaEventDisableTiming);
        cudaEventCreateWithFlags(&evW,    cudaEventDisableTiming);
        cudaFuncSetAttribute(k_gemm_mma, cudaFuncAttributeMaxDynamicSharedMemorySize, SMEM_GEMM);
        inited = 1;
    }

    void *p_pool, *p_deg, *p_scal;
    cudaGetSymbolAddress(&p_pool,  g_pool);
    cudaGetSymbolAddress(&p_deg,   g_deg);
    cudaGetSymbolAddress(&p_scal,  g_scal);

    // fork
    cudaEventRecord(evFork, 0);
    cudaStreamWaitEvent(s1, evFork, 0);
    cudaStreamWaitEvent(s2, evFork, 0);

    // s1: CSR build + scalar reductions + small memsets
    cudaMemsetAsync(p_pool, 0, OUTD * sizeof(float), s1);
    cudaMemsetAsync(p_deg,  0, (size_t)N * sizeof(int), s1);
    cudaMemsetAsync(p_scal, 0, sizeof(float), s1);
    k_count<<<(E + 255) / 256, 256, 0, s1>>>(ei, E);
    k_scan<<<1, 1024, 0, s1>>>(N);
    k_fill<<<(ET + 255) / 256, 256, 0, s1>>>(ei, E, N);
    k_easum<<<64, 256, 0, s1>>>(ea, E);
    k_kcoef<<<1, 256, 0, s1>>>(Wedge, att_edge);
    cudaEventRecord(evCSR, s1);

    // s2: weight conversion (coalesced transpose)
    {
        dim3 gw2(OUTD / 32, EMBED / 32);
        k_cvtW<<<gw2, 256, 0, s2>>>(W);
    }
    cudaEventRecord(evW, s2);

    // main: GEMM (in-kernel A conversion + fused logits) -> alphaexp -> agg -> clf
    cudaStreamWaitEvent(0, evW, 0);
    dim3 gg(OUTD / 128, PADN / 128);
    k_gemm_mma<<<gg, 256, SMEM_GEMM>>>(N, x, att_src, att_dst);

    cudaStreamWaitEvent(0, evCSR, 0);
    int totalEH = ET * HEADS;
    k_alphaexp<<<(totalEH + 255) / 256, 256>>>(ei, ea, E, N);
    k_agg<<<(N * 32 + 255) / 256, 256>>>(N, tip, iip);

    k_clf<<<1, 256>>>(bias, tip, iip, clfW, clfb, N, out);
}

// round 12
// speedup vs baseline: 1.0795x; 1.0795x over previous
#include <cuda_runtime.h>
#include <cuda_bf16.h>
#include <cuda_fp16.h>
#include <cstdint>

#define EMBED 768
#define OUTD  1024
#define HEADS 8
#define HD    128
#define MAXN  10000
#define MAXE  160000
#define MAXET (MAXN + MAXE)
#define PADN  10112            // 79 * 128

// ---------------- scratch ----------------
__device__ __half   g_xsh[(size_t)MAXN * OUTD];   // fp16 xs for aggregation (20 MB)
__device__ float    g_h[MAXN * OUTD];             // only rows text/image are written
__device__ float    g_asrc[MAXN * HEADS];
__device__ float    g_adst[MAXN * HEADS];
__device__ float    g_edge[MAXET * HEADS];
__device__ float    g_scal[16];                   // [0]=sum(ea), [1..8]=k[h]
__device__ float    g_pool[OUTD];
// CSR by dst
__device__ int      g_deg[MAXN];
__device__ int      g_off[MAXN + 1];
__device__ int      g_cur[MAXN];
__device__ unsigned g_csr[MAXET];                 // (edge_id << 14) | src
// bf16-split W^T for tensor-core GEMM
__device__ __nv_bfloat16 g_Whi[(size_t)OUTD * EMBED];
__device__ __nv_bfloat16 g_Wlo[(size_t)OUTD * EMBED];

// ---------------- PTX helpers ----------------
__device__ __forceinline__ uint32_t smem_u32(const void* p) {
    uint32_t a;
    asm("{ .reg .u64 t; cvta.to.shared.u64 t, %1; cvt.u32.u64 %0, t; }" : "=r"(a) : "l"(p));
    return a;
}
__device__ __forceinline__ void cp16(uint32_t s, const void* g) {
    asm volatile("cp.async.cg.shared.global [%0], [%1], 16;" :: "r"(s), "l"(g));
}
__device__ __forceinline__ void cp_commit() {
    asm volatile("cp.async.commit_group;" ::: "memory");
}
template <int N>
__device__ __forceinline__ void cp_wait() {
    asm volatile("cp.async.wait_group %0;" :: "n"(N) : "memory");
}
__device__ __forceinline__ void ldsm4(uint32_t& r0, uint32_t& r1, uint32_t& r2, uint32_t& r3,
                                      uint32_t addr) {
    asm volatile("ldmatrix.sync.aligned.m8n8.x4.shared.b16 {%0,%1,%2,%3}, [%4];"
                 : "=r"(r0), "=r"(r1), "=r"(r2), "=r"(r3) : "r"(addr));
}
__device__ __forceinline__ void mma16816(float* d, const uint32_t* a, const uint32_t* b) {
    asm volatile(
        "mma.sync.aligned.m16n8k16.row.col.f32.bf16.bf16.f32 "
        "{%0,%1,%2,%3}, {%4,%5,%6,%7}, {%8,%9}, {%0,%1,%2,%3};"
        : "+f"(d[0]), "+f"(d[1]), "+f"(d[2]), "+f"(d[3])
        : "r"(a[0]), "r"(a[1]), "r"(a[2]), "r"(a[3]), "r"(b[0]), "r"(b[1]));
}

__device__ __forceinline__ uint32_t sw_off(int row, int c) {
    return (uint32_t)(row * 64 + ((c ^ ((row >> 1) & 3)) << 4));
}

// ---------------- K0b: W^T split via smem tile transpose ----------------
__global__ __launch_bounds__(256)
void k_cvtW(const float* __restrict__ W) {
    __shared__ float tile[32][33];
    const int k0 = blockIdx.y * 32;
    const int n0 = blockIdx.x * 32;
    const int tx = threadIdx.x & 31, ty = threadIdx.x >> 5;
    #pragma unroll
    for (int i = 0; i < 32; i += 8)
        tile[ty + i][tx] = W[(size_t)(k0 + ty + i) * OUTD + n0 + tx];
    __syncthreads();
    #pragma unroll
    for (int i = 0; i < 32; i += 8) {
        float v = tile[tx][ty + i];
        __nv_bfloat16 hi = __float2bfloat16(v);
        __nv_bfloat16 lo = __float2bfloat16(v - __bfloat162float(hi));
        g_Whi[(size_t)(n0 + ty + i) * EMBED + k0 + tx] = hi;
        g_Wlo[(size_t)(n0 + ty + i) * EMBED + k0 + tx] = lo;
    }
}

// ---------------- K2: HMMA bf16-split GEMM, in-kernel A conversion, fused logits ----------------
#define KCH    32
#define NCHUNK (EMBED / KCH)      // 24
#define TILEB  (128 * 64)         // 8 KB
#define STAGEB (4 * TILEB)        // 32 KB
#define NSTAGE 3
#define SMEM_GEMM (NSTAGE * STAGEB)

__global__ __launch_bounds__(256, 2)
void k_gemm_mma(int M, const float* __restrict__ x,
                const float* __restrict__ att_src,
                const float* __restrict__ att_dst) {
    extern __shared__ char smem[];
    const uint32_t sb = smem_u32(smem);
    const int tid = threadIdx.x;
    const int wid = tid >> 5, lane = tid & 31;
    const int warp_m = wid & 3;
    const int warp_n = wid >> 2;
    const int rowBase = blockIdx.y * 128;
    const int colBase = blockIdx.x * 128;
    const int head = colBase >> 7;

    const __nv_bfloat16* srcB[2] = {
        g_Whi + (size_t)colBase * EMBED,
        g_Wlo + (size_t)colBase * EMBED };

    const int chunk0 = tid * 2;
    const int row0 = chunk0 >> 2, cc0 = chunk0 & 3;
    const int row1 = (chunk0 + 1) >> 2, cc1 = (chunk0 + 1) & 3;
    const uint32_t so0 = sw_off(row0, cc0);
    const uint32_t so1 = sw_off(row1, cc1);
    const int rowg0 = rowBase + row0, rowg1 = rowBase + row1;
    const float4* xv = (const float4*)x;

    float af[16];

    auto ldA = [&](int c) {
        int kb = c * 8;
        if (rowg0 < M) {
            *(float4*)&af[0] = xv[(size_t)rowg0 * (EMBED / 4) + kb + cc0 * 2];
            *(float4*)&af[4] = xv[(size_t)rowg0 * (EMBED / 4) + kb + cc0 * 2 + 1];
        } else {
            #pragma unroll
            for (int j = 0; j < 8; j++) af[j] = 0.f;
        }
        if (rowg1 < M) {
            *(float4*)&af[8]  = xv[(size_t)rowg1 * (EMBED / 4) + kb + cc1 * 2];
            *(float4*)&af[12] = xv[(size_t)rowg1 * (EMBED / 4) + kb + cc1 * 2 + 1];
        } else {
            #pragma unroll
            for (int j = 8; j < 16; j++) af[j] = 0.f;
        }
    };

    auto stsA = [&](int s) {
        const uint32_t stOff = (uint32_t)(s * STAGEB);
        #pragma unroll
        for (int ch = 0; ch < 2; ch++) {
            const float* f = &af[ch * 8];
            __nv_bfloat162 H[4], L[4];
            #pragma unroll
            for (int j = 0; j < 4; j++) {
                float2 p = make_float2(f[2 * j], f[2 * j + 1]);
                __nv_bfloat162 h = __float22bfloat162_rn(p);
                H[j] = h;
                float2 r = make_float2(p.x - __bfloat162float(h.x),
                                       p.y - __bfloat162float(h.y));
                L[j] = __float22bfloat162_rn(r);
            }
            uint32_t off = (ch == 0) ? so0 : so1;
            *(uint4*)(smem + stOff + off)         = *(uint4*)H;
            *(uint4*)(smem + stOff + TILEB + off) = *(uint4*)L;
        }
    };

    auto cpB = [&](int c, int s) {
        const uint32_t base = sb + s * STAGEB;
        const int k0 = c * KCH;
        #pragma unroll
        for (int t = 0; t < 2; t++) {
            const __nv_bfloat16* g = srcB[t] + k0;
            cp16(base + (2 + t) * TILEB + so0, g + (size_t)row0 * EMBED + cc0 * 8);
            cp16(base + (2 + t) * TILEB + so1, g + (size_t)row1 * EMBED + cc1 * 8);
        }
        cp_commit();
    };

    ldA(0);
    cpB(0, 0);
    cpB(1, 1);

    float acc[2][8][4];
    #pragma unroll
    for (int mb = 0; mb < 2; mb++)
        #pragma unroll
        for (int nb = 0; nb < 8; nb++)
            #pragma unroll
            for (int j = 0; j < 4; j++) acc[mb][nb][j] = 0.f;

    const int l_tile = lane >> 3, l_rin = lane & 7;

    for (int c = 0; c < NCHUNK; c++) {
        const int s = c % NSTAGE;
        stsA(s);
        if (c + 1 < NCHUNK) cp_wait<1>(); else cp_wait<0>();
        __syncthreads();
        if (c + 1 < NCHUNK) ldA(c + 1);
        if (c + 2 < NCHUNK) cpB(c + 2, (c + 2) % NSTAGE);

        const uint32_t base = sb + s * STAGEB;
        #pragma unroll
        for (int ks = 0; ks < 2; ks++) {
            uint32_t a[2][2][4];
            uint32_t b[2][8][2];
            #pragma unroll
            for (int v = 0; v < 2; v++)
                #pragma unroll
                for (int mb = 0; mb < 2; mb++) {
                    int r = warp_m * 32 + mb * 16 + ((l_tile & 1) << 3) + l_rin;
                    int cch = ks * 2 + (l_tile >> 1);
                    ldsm4(a[v][mb][0], a[v][mb][1], a[v][mb][2], a[v][mb][3],
                          base + v * TILEB + sw_off(r, cch));
                }
            #pragma unroll
            for (int v = 0; v < 2; v++)
                #pragma unroll
                for (int p = 0; p < 4; p++) {
                    int r = warp_n * 64 + p * 16 + ((l_tile >> 1) << 3) + l_rin;
                    int cch = ks * 2 + (l_tile & 1);
                    ldsm4(b[v][p * 2][0], b[v][p * 2][1],
                          b[v][p * 2 + 1][0], b[v][p * 2 + 1][1],
                          base + (2 + v) * TILEB + sw_off(r, cch));
                }
            #pragma unroll
            for (int mb = 0; mb < 2; mb++)
                #pragma unroll
                for (int nb = 0; nb < 8; nb++) {
                    mma16816(acc[mb][nb], a[0][mb], b[0][nb]);
                    mma16816(acc[mb][nb], a[0][mb], b[1][nb]);
                    mma16816(acc[mb][nb], a[1][mb], b[0][nb]);
                }
        }
    }

    // ---- epilogue: logits via smem + fp16 xs store ----
    __syncthreads();
    float* sasrc = (float*)smem;
    float* sadst = sasrc + 128;
    ((float*)smem)[tid] = 0.f;
    __syncthreads();

    const int tr = lane >> 2, tc = (lane & 3) * 2;

    float as[16], ad[16];
    #pragma unroll
    for (int nb = 0; nb < 8; nb++)
        #pragma unroll
        for (int j = 0; j < 2; j++) {
            int col = warp_n * 64 + nb * 8 + tc + j;
            as[nb * 2 + j] = att_src[head * HD + col];
            ad[nb * 2 + j] = att_dst[head * HD + col];
        }

    #pragma unroll
    for (int mb = 0; mb < 2; mb++) {
        #pragma unroll
        for (int half = 0; half < 2; half++) {
            int rloc = warp_m * 32 + mb * 16 + half * 8 + tr;
            int row = rowBase + rloc;
            float ps = 0.f, pd = 0.f;
            #pragma unroll
            for (int nb = 0; nb < 8; nb++)
                #pragma unroll
                for (int j = 0; j < 2; j++) {
                    float v = acc[mb][nb][half * 2 + j];
                    ps += v * as[nb * 2 + j];
                    pd += v * ad[nb * 2 + j];
                }
            #pragma unroll
            for (int o = 1; o < 4; o <<= 1) {
                ps += __shfl_xor_sync(0xffffffffu, ps, o);
                pd += __shfl_xor_sync(0xffffffffu, pd, o);
            }
            if (row < M) {
                if ((lane & 3) == 0) {
                    atomicAdd(&sasrc[rloc], ps);
                    atomicAdd(&sadst[rloc], pd);
                }
                __half* dst = &g_xsh[(size_t)row * OUTD + colBase + warp_n * 64 + tc];
                #pragma unroll
                for (int nb = 0; nb < 8; nb++) {
                    __half2 v = __floats2half2_rn(acc[mb][nb][half * 2],
                                                  acc[mb][nb][half * 2 + 1]);
                    *(__half2*)(dst + nb * 8) = v;
                }
            }
        }
    }
    __syncthreads();
    if (tid < 128) {
        int row = rowBase + tid;
        if (row < M) {
            g_asrc[row * HEADS + head] = sasrc[tid];
            g_adst[row * HEADS + head] = sadst[tid];
        }
    }
}

// ---------------- K1a: parallel sum of ea ----------------
__global__ void k_easum(const float* __restrict__ ea, int E) {
    __shared__ float sh[256];
    float s = 0.f;
    for (int i = blockIdx.x * 256 + threadIdx.x; i < E; i += gridDim.x * 256) s += ea[i];
    sh[threadIdx.x] = s; __syncthreads();
    for (int o = 128; o; o >>= 1) {
        if (threadIdx.x < o) sh[threadIdx.x] += sh[threadIdx.x + o];
        __syncthreads();
    }
    if (threadIdx.x == 0) atomicAdd(&g_scal[0], sh[0]);
}

// ---------------- K1b: per-head edge coefficient k[h] ----------------
__global__ void k_kcoef(const float* __restrict__ Wedge,
                        const float* __restrict__ att_edge) {
    int wid = threadIdx.x >> 5, lane = threadIdx.x & 31;
    float s = 0.f;
    for (int c = lane; c < HD; c += 32)
        s += Wedge[wid * HD + c] * att_edge[wid * HD + c];
    #pragma unroll
    for (int o = 16; o; o >>= 1) s += __shfl_down_sync(0xffffffffu, s, o);
    if (lane == 0) g_scal[1 + wid] = s;
}

// ---------------- CSR build ----------------
__global__ void k_count(const int* __restrict__ ei, int E) {
    int e = blockIdx.x * blockDim.x + threadIdx.x;
    if (e < E) atomicAdd(&g_deg[ei[E + e]], 1);
}

__global__ __launch_bounds__(1024)
void k_scan(int N) {
    __shared__ int sh[1024];
    int t = threadIdx.x;
    int chunk = (N + 1023) / 1024;
    int s0 = min(t * chunk, N), s1 = min(s0 + chunk, N);
    int sum = 0;
    for (int n = s0; n < s1; n++) sum += g_deg[n] + 1;
    sh[t] = sum; __syncthreads();
    for (int o = 1; o < 1024; o <<= 1) {
        int v = (t >= o) ? sh[t - o] : 0;
        __syncthreads();
        sh[t] += v;
        __syncthreads();
    }
    int run = (t == 0) ? 0 : sh[t - 1];
    for (int n = s0; n < s1; n++) {
        g_off[n] = run;
        g_cur[n] = run;
        run += g_deg[n] + 1;
    }
    if (t == 1023) g_off[N] = sh[1023];
}

__global__ void k_fill(const int* __restrict__ ei, int E, int N) {
    int t = blockIdx.x * blockDim.x + threadIdx.x;
    if (t >= E + N) return;
    int d, s;
    if (t < E) { d = ei[E + t]; s = ei[t]; }
    else       { d = s = t - E; }
    int pos = atomicAdd(&g_cur[d], 1);
    g_csr[pos] = ((unsigned)t << 14) | (unsigned)s;
}

// ---------------- K4: fused alpha+exp (denom computed in agg) ----------------
__global__ void k_alphaexp(const int* __restrict__ ei, const float* __restrict__ ea,
                           int E, int N) {
    int t = blockIdx.x * blockDim.x + threadIdx.x;
    int total = (E + N) * HEADS;
    if (t >= total) return;
    int e = t >> 3, h = t & 7;
    int s, d; float av;
    if (e < E) { s = ei[e]; d = ei[E + e]; av = ea[e]; }
    else       { s = d = e - E;            av = g_scal[0] / (float)E; }
    float a = g_asrc[s * HEADS + h] + g_adst[d * HEADS + h] + av * g_scal[1 + h];
    a = (a >= 0.f) ? a : 0.2f * a;
    g_edge[t] = __expf(a);
}

// ---------------- K6: CSR agg (fp16 gathers) + in-warp denom + fused mean-pool ----------------
__global__ __launch_bounds__(256)
void k_agg(int N, const int* __restrict__ tip, const int* __restrict__ iip) {
    __shared__ float spool[OUTD];
    const int tid = threadIdx.x;
    for (int j = tid; j < OUTD; j += 256) spool[j] = 0.f;
    __syncthreads();

    int gw = (blockIdx.x * 256 + tid) >> 5;
    int lane = tid & 31;
    if (gw < N) {
        const int st = g_off[gw], en = g_off[gw + 1];
        const int hi4 = lane >> 4;          // which head within the pass pair

        float acc[4][8];
        float dsum[4];
        #pragma unroll
        for (int p = 0; p < 4; p++) {
            dsum[p] = 0.f;
            #pragma unroll
            for (int j = 0; j < 8; j++) acc[p][j] = 0.f;
        }

        #pragma unroll 2
        for (int i = st; i < en; i++) {
            unsigned pk = g_csr[i];
            int e = pk >> 14, s = pk & 0x3FFF;
            const uint4* rowq = (const uint4*)&g_xsh[(size_t)s * OUTD];
            const float* we = &g_edge[(size_t)e * HEADS];
            #pragma unroll
            for (int p = 0; p < 4; p++) {
                float w = we[p * 2 + hi4];
                uint4 v = rowq[p * 32 + lane];
                const __half2* hv = (const __half2*)&v;
                dsum[p] += w;
                #pragma unroll
                for (int q = 0; q < 4; q++) {
                    float2 f = __half22float2(hv[q]);
                    acc[p][q * 2]     += w * f.x;
                    acc[p][q * 2 + 1] += w * f.y;
                }
            }
        }
        #pragma unroll
        for (int p = 0; p < 4; p++) {
            float inv = 1.f / dsum[p];
            #pragma unroll
            for (int j = 0; j < 8; j++) acc[p][j] *= inv;
        }

        // conflict-free smem pool accumulation (lane-rotated j)
        #pragma unroll
        for (int p = 0; p < 4; p++)
            #pragma unroll
            for (int jj = 0; jj < 8; jj++) {
                int j = (jj + lane) & 7;
                atomicAdd(&spool[p * 256 + lane * 8 + j], acc[p][j]);
            }

        int t = tip[0], im = iip[0];
        if (gw == t || gw == im) {
            float* out = &g_h[(size_t)gw * OUTD];
            #pragma unroll
            for (int p = 0; p < 4; p++) {
                *(float4*)&out[p * 256 + lane * 8]     = *(float4*)&acc[p][0];
                *(float4*)&out[p * 256 + lane * 8 + 4] = *(float4*)&acc[p][4];
            }
        }
    }
    __syncthreads();
    for (int j = tid; j < OUTD; j += 256) atomicAdd(&g_pool[j], spool[j]);
}

// ---------------- K8: fused vector + classifier ----------------
__global__ void k_clf(const float* __restrict__ bias,
                      const int* __restrict__ tip, const int* __restrict__ iip,
                      const float* __restrict__ clfW, const float* __restrict__ clfb,
                      int N, float* __restrict__ out) {
    __shared__ float s0[256], s1[256];
    int t = threadIdx.x;
    int ti = tip[0], im = iip[0];
    float a0 = 0.f, a1 = 0.f;
    for (int j = t; j < 3 * OUTD; j += 256) {
        int jj = j & (OUTD - 1);
        int seg = j >> 10;
        float b = bias[jj];
        float f;
        if (seg == 0)      f = g_pool[jj] / (float)N + b;
        else if (seg == 1) f = g_h[(size_t)ti * OUTD + jj] + b;
        else               f = g_h[(size_t)im * OUTD + jj] + b;
        a0 += f * clfW[2 * j];
        a1 += f * clfW[2 * j + 1];
    }
    s0[t] = a0; s1[t] = a1; __syncthreads();
    for (int o = 128; o; o >>= 1) {
        if (t < o) { s0[t] += s0[t + o]; s1[t] += s1[t + o]; }
        __syncthreads();
    }
    if (t == 0) {
        out[0] = s0[0] + clfb[0];
        out[1] = s1[0] + clfb[1];
    }
}

// ---------------- launch ----------------
extern "C" void kernel_launch(void* const* d_in, const int* in_sizes, int n_in,
                              void* d_out, int out_size) {
    const float* x        = (const float*)d_in[0];
    const int*   ei       = (const int*)  d_in[1];
    const float* ea       = (const float*)d_in[2];
    const int*   tip      = (const int*)  d_in[3];
    const int*   iip      = (const int*)  d_in[4];
    const float* W        = (const float*)d_in[5];
    const float* att_src  = (const float*)d_in[6];
    const float* att_dst  = (const float*)d_in[7];
    const float* Wedge    = (const float*)d_in[8];
    const float* att_edge = (const float*)d_in[9];
    const float* bias     = (const float*)d_in[10];
    const float* clfW     = (const float*)d_in[11];
    const float* clfb     = (const float*)d_in[12];
    float* out = (float*)d_out;

    int N  = in_sizes[0] / EMBED;
    int E  = in_sizes[1] / 2;
    int ET = E + N;

    static cudaStream_t s1, s2;
    static cudaEvent_t evFork, evCSR, evW;
    static int inited = 0;
    if (!inited) {
        cudaStreamCreateWithFlags(&s1, cudaStreamNonBlocking);
        cudaStreamCreateWithFlags(&s2, cudaStreamNonBlocking);
        cudaEventCreateWithFlags(&evFork, cudaEventDisableTiming);
        cudaEventCreateWithFlags(&evCSR,  cudaEventDisableTiming);
        cudaEventCreateWithFlags(&evW,    cudaEventDisableTiming);
        cudaFuncSetAttribute(k_gemm_mma, cudaFuncAttributeMaxDynamicSharedMemorySize, SMEM_GEMM);
        inited = 1;
    }

    void *p_pool, *p_deg, *p_scal;
    cudaGetSymbolAddress(&p_pool,  g_pool);
    cudaGetSymbolAddress(&p_deg,   g_deg);
    cudaGetSymbolAddress(&p_scal,  g_scal);

    // fork
    cudaEventRecord(evFork, 0);
    cudaStreamWaitEvent(s1, evFork, 0);
    cudaStreamWaitEvent(s2, evFork, 0);

    // s1: CSR build + scalar reductions + small memsets
    cudaMemsetAsync(p_pool, 0, OUTD * sizeof(float), s1);
    cudaMemsetAsync(p_deg,  0, (size_t)N * sizeof(int), s1);
    cudaMemsetAsync(p_scal, 0, sizeof(float), s1);
    k_count<<<(E + 255) / 256, 256, 0, s1>>>(ei, E);
    k_scan<<<1, 1024, 0, s1>>>(N);
    k_fill<<<(ET + 255) / 256, 256, 0, s1>>>(ei, E, N);
    k_easum<<<64, 256, 0, s1>>>(ea, E);
    k_kcoef<<<1, 256, 0, s1>>>(Wedge, att_edge);
    cudaEventRecord(evCSR, s1);

    // s2: weight conversion (coalesced transpose)
    {
        dim3 gw2(OUTD / 32, EMBED / 32);
        k_cvtW<<<gw2, 256, 0, s2>>>(W);
    }
    cudaEventRecord(evW, s2);

    // main: GEMM (in-kernel A conversion + fused logits + fp16 xs) -> alphaexp -> agg -> clf
    cudaStreamWaitEvent(0, evW, 0);
    dim3 gg(OUTD / 128, PADN / 128);
    k_gemm_mma<<<gg, 256, SMEM_GEMM>>>(N, x, att_src, att_dst);

    cudaStreamWaitEvent(0, evCSR, 0);
    int totalEH = ET * HEADS;
    k_alphaexp<<<(totalEH + 255) / 256, 256>>>(ei, ea, E, N);
    k_agg<<<(N * 32 + 255) / 256, 256>>>(N, tip, iip);

    k_clf<<<1, 256>>>(bias, tip, iip, clfW, clfb, N, out);
}

// round 13
// speedup vs baseline: 1.2686x; 1.1752x over previous
#include <cuda_runtime.h>
#include <cuda_fp16.h>
#include <cstdint>

#define EMBED 768
#define OUTD  1024
#define HEADS 8
#define HD    128
#define MAXN  10000
#define MAXE  160000
#define MAXET (MAXN + MAXE)
#define PADN  10112            // 79 * 128

// ---------------- scratch ----------------
__device__ __half   g_xsh[(size_t)MAXN * OUTD];   // fp16 xs for aggregation (20 MB)
__device__ float    g_h[MAXN * OUTD];             // only rows text/image are written
__device__ float    g_asrc[MAXN * HEADS];
__device__ float    g_adst[MAXN * HEADS];
__device__ float    g_edge[MAXET * HEADS];
__device__ float    g_scal[16];                   // [0]=sum(ea), [1..8]=k[h]
__device__ float    g_pool[OUTD];
// CSR by dst
__device__ int      g_deg[MAXN];
__device__ int      g_off[MAXN + 1];
__device__ int      g_cur[MAXN];
__device__ unsigned g_csr[MAXET];                 // (edge_id << 14) | src
// fp16 W^T for tensor-core GEMM
__device__ __half   g_Wh[(size_t)OUTD * EMBED];   // W^T [n][k], fp16

// ---------------- PTX helpers ----------------
__device__ __forceinline__ uint32_t smem_u32(const void* p) {
    uint32_t a;
    asm("{ .reg .u64 t; cvta.to.shared.u64 t, %1; cvt.u32.u64 %0, t; }" : "=r"(a) : "l"(p));
    return a;
}
__device__ __forceinline__ void cp16(uint32_t s, const void* g) {
    asm volatile("cp.async.cg.shared.global [%0], [%1], 16;" :: "r"(s), "l"(g));
}
__device__ __forceinline__ void cp_commit() {
    asm volatile("cp.async.commit_group;" ::: "memory");
}
template <int N>
__device__ __forceinline__ void cp_wait() {
    asm volatile("cp.async.wait_group %0;" :: "n"(N) : "memory");
}
__device__ __forceinline__ void ldsm4(uint32_t& r0, uint32_t& r1, uint32_t& r2, uint32_t& r3,
                                      uint32_t addr) {
    asm volatile("ldmatrix.sync.aligned.m8n8.x4.shared.b16 {%0,%1,%2,%3}, [%4];"
                 : "=r"(r0), "=r"(r1), "=r"(r2), "=r"(r3) : "r"(addr));
}
__device__ __forceinline__ void mma16816h(float* d, const uint32_t* a, const uint32_t* b) {
    asm volatile(
        "mma.sync.aligned.m16n8k16.row.col.f32.f16.f16.f32 "
        "{%0,%1,%2,%3}, {%4,%5,%6,%7}, {%8,%9}, {%0,%1,%2,%3};"
        : "+f"(d[0]), "+f"(d[1]), "+f"(d[2]), "+f"(d[3])
        : "r"(a[0]), "r"(a[1]), "r"(a[2]), "r"(a[3]), "r"(b[0]), "r"(b[1]));
}

__device__ __forceinline__ uint32_t sw_off(int row, int c) {
    return (uint32_t)(row * 64 + ((c ^ ((row >> 1) & 3)) << 4));
}

// ---------------- K0b: W^T fp16 via smem tile transpose ----------------
__global__ __launch_bounds__(256)
void k_cvtW(const float* __restrict__ W) {
    __shared__ float tile[32][33];
    const int k0 = blockIdx.y * 32;
    const int n0 = blockIdx.x * 32;
    const int tx = threadIdx.x & 31, ty = threadIdx.x >> 5;
    #pragma unroll
    for (int i = 0; i < 32; i += 8)
        tile[ty + i][tx] = W[(size_t)(k0 + ty + i) * OUTD + n0 + tx];
    __syncthreads();
    #pragma unroll
    for (int i = 0; i < 32; i += 8)
        g_Wh[(size_t)(n0 + ty + i) * EMBED + k0 + tx] = __float2half(tile[tx][ty + i]);
}

// ---------------- K2: HMMA fp16 2-term GEMM, in-kernel A conversion, fused logits ----------------
#define KCH    32
#define NCHUNK (EMBED / KCH)      // 24
#define TILEB  (128 * 64)         // 8 KB
#define STAGEB (3 * TILEB)        // Ahi, Alo, B = 24 KB
#define NSTAGE 3
#define SMEM_GEMM (NSTAGE * STAGEB)

__global__ __launch_bounds__(256, 2)
void k_gemm_mma(int M, const float* __restrict__ x,
                const float* __restrict__ att_src,
                const float* __restrict__ att_dst) {
    extern __shared__ char smem[];
    const uint32_t sb = smem_u32(smem);
    const int tid = threadIdx.x;
    const int wid = tid >> 5, lane = tid & 31;
    const int warp_m = wid & 3;
    const int warp_n = wid >> 2;
    const int rowBase = blockIdx.y * 128;
    const int colBase = blockIdx.x * 128;
    const int head = colBase >> 7;

    const __half* srcB = g_Wh + (size_t)colBase * EMBED;

    const int chunk0 = tid * 2;
    const int row0 = chunk0 >> 2, cc0 = chunk0 & 3;
    const int row1 = (chunk0 + 1) >> 2, cc1 = (chunk0 + 1) & 3;
    const uint32_t so0 = sw_off(row0, cc0);
    const uint32_t so1 = sw_off(row1, cc1);
    const int rowg0 = rowBase + row0, rowg1 = rowBase + row1;
    const float4* xv = (const float4*)x;

    float af[16];

    auto ldA = [&](int c) {
        int kb = c * 8;
        if (rowg0 < M) {
            *(float4*)&af[0] = xv[(size_t)rowg0 * (EMBED / 4) + kb + cc0 * 2];
            *(float4*)&af[4] = xv[(size_t)rowg0 * (EMBED / 4) + kb + cc0 * 2 + 1];
        } else {
            #pragma unroll
            for (int j = 0; j < 8; j++) af[j] = 0.f;
        }
        if (rowg1 < M) {
            *(float4*)&af[8]  = xv[(size_t)rowg1 * (EMBED / 4) + kb + cc1 * 2];
            *(float4*)&af[12] = xv[(size_t)rowg1 * (EMBED / 4) + kb + cc1 * 2 + 1];
        } else {
            #pragma unroll
            for (int j = 8; j < 16; j++) af[j] = 0.f;
        }
    };

    auto stsA = [&](int s) {
        const uint32_t stOff = (uint32_t)(s * STAGEB);
        #pragma unroll
        for (int ch = 0; ch < 2; ch++) {
            const float* f = &af[ch * 8];
            __half2 H[4], L[4];
            #pragma unroll
            for (int j = 0; j < 4; j++) {
                float2 p = make_float2(f[2 * j], f[2 * j + 1]);
                __half2 h = __floats2half2_rn(p.x, p.y);
                H[j] = h;
                float2 hf = __half22float2(h);
                L[j] = __floats2half2_rn(p.x - hf.x, p.y - hf.y);
            }
            uint32_t off = (ch == 0) ? so0 : so1;
            *(uint4*)(smem + stOff + off)         = *(uint4*)H;   // Ahi tile 0
            *(uint4*)(smem + stOff + TILEB + off) = *(uint4*)L;   // Alo tile 1
        }
    };

    auto cpB = [&](int c, int s) {
        const uint32_t base = sb + s * STAGEB;
        const int k0 = c * KCH;
        cp16(base + 2 * TILEB + so0, srcB + (size_t)row0 * EMBED + k0 + cc0 * 8);
        cp16(base + 2 * TILEB + so1, srcB + (size_t)row1 * EMBED + k0 + cc1 * 8);
        cp_commit();
    };

    ldA(0);
    cpB(0, 0);
    cpB(1, 1);

    float acc[2][8][4];
    #pragma unroll
    for (int mb = 0; mb < 2; mb++)
        #pragma unroll
        for (int nb = 0; nb < 8; nb++)
            #pragma unroll
            for (int j = 0; j < 4; j++) acc[mb][nb][j] = 0.f;

    const int l_tile = lane >> 3, l_rin = lane & 7;

    for (int c = 0; c < NCHUNK; c++) {
        const int s = c % NSTAGE;
        stsA(s);
        if (c + 1 < NCHUNK) cp_wait<1>(); else cp_wait<0>();
        __syncthreads();
        if (c + 1 < NCHUNK) ldA(c + 1);
        if (c + 2 < NCHUNK) cpB(c + 2, (c + 2) % NSTAGE);

        const uint32_t base = sb + s * STAGEB;
        #pragma unroll
        for (int ks = 0; ks < 2; ks++) {
            uint32_t a[2][2][4];
            uint32_t b[8][2];
            #pragma unroll
            for (int v = 0; v < 2; v++)
                #pragma unroll
                for (int mb = 0; mb < 2; mb++) {
                    int r = warp_m * 32 + mb * 16 + ((l_tile & 1) << 3) + l_rin;
                    int cch = ks * 2 + (l_tile >> 1);
                    ldsm4(a[v][mb][0], a[v][mb][1], a[v][mb][2], a[v][mb][3],
                          base + v * TILEB + sw_off(r, cch));
                }
            #pragma unroll
            for (int p = 0; p < 4; p++) {
                int r = warp_n * 64 + p * 16 + ((l_tile >> 1) << 3) + l_rin;
                int cch = ks * 2 + (l_tile & 1);
                ldsm4(b[p * 2][0], b[p * 2][1],
                      b[p * 2 + 1][0], b[p * 2 + 1][1],
                      base + 2 * TILEB + sw_off(r, cch));
            }
            #pragma unroll
            for (int mb = 0; mb < 2; mb++)
                #pragma unroll
                for (int nb = 0; nb < 8; nb++) {
                    mma16816h(acc[mb][nb], a[0][mb], b[nb]);   // Ahi * B
                    mma16816h(acc[mb][nb], a[1][mb], b[nb]);   // Alo * B
                }
        }
    }

    // ---- epilogue: logits via smem + fp16 xs store ----
    __syncthreads();
    float* sasrc = (float*)smem;
    float* sadst = sasrc + 128;
    ((float*)smem)[tid] = 0.f;
    __syncthreads();

    const int tr = lane >> 2, tc = (lane & 3) * 2;

    float as[16], ad[16];
    #pragma unroll
    for (int nb = 0; nb < 8; nb++)
        #pragma unroll
        for (int j = 0; j < 2; j++) {
            int col = warp_n * 64 + nb * 8 + tc + j;
            as[nb * 2 + j] = att_src[head * HD + col];
            ad[nb * 2 + j] = att_dst[head * HD + col];
        }

    #pragma unroll
    for (int mb = 0; mb < 2; mb++) {
        #pragma unroll
        for (int half = 0; half < 2; half++) {
            int rloc = warp_m * 32 + mb * 16 + half * 8 + tr;
            int row = rowBase + rloc;
            float ps = 0.f, pd = 0.f;
            #pragma unroll
            for (int nb = 0; nb < 8; nb++)
                #pragma unroll
                for (int j = 0; j < 2; j++) {
                    float v = acc[mb][nb][half * 2 + j];
                    ps += v * as[nb * 2 + j];
                    pd += v * ad[nb * 2 + j];
                }
            #pragma unroll
            for (int o = 1; o < 4; o <<= 1) {
                ps += __shfl_xor_sync(0xffffffffu, ps, o);
                pd += __shfl_xor_sync(0xffffffffu, pd, o);
            }
            if (row < M) {
                if ((lane & 3) == 0) {
                    atomicAdd(&sasrc[rloc], ps);
                    atomicAdd(&sadst[rloc], pd);
                }
                __half* dst = &g_xsh[(size_t)row * OUTD + colBase + warp_n * 64 + tc];
                #pragma unroll
                for (int nb = 0; nb < 8; nb++) {
                    __half2 v = __floats2half2_rn(acc[mb][nb][half * 2],
                                                  acc[mb][nb][half * 2 + 1]);
                    *(__half2*)(dst + nb * 8) = v;
                }
            }
        }
    }
    __syncthreads();
    if (tid < 128) {
        int row = rowBase + tid;
        if (row < M) {
            g_asrc[row * HEADS + head] = sasrc[tid];
            g_adst[row * HEADS + head] = sadst[tid];
        }
    }
}

// ---------------- K1a: parallel sum of ea ----------------
__global__ void k_easum(const float* __restrict__ ea, int E) {
    __shared__ float sh[256];
    float s = 0.f;
    for (int i = blockIdx.x * 256 + threadIdx.x; i < E; i += gridDim.x * 256) s += ea[i];
    sh[threadIdx.x] = s; __syncthreads();
    for (int o = 128; o; o >>= 1) {
        if (threadIdx.x < o) sh[threadIdx.x] += sh[threadIdx.x + o];
        __syncthreads();
    }
    if (threadIdx.x == 0) atomicAdd(&g_scal[0], sh[0]);
}

// ---------------- K1b: per-head edge coefficient k[h] ----------------
__global__ void k_kcoef(const float* __restrict__ Wedge,
                        const float* __restrict__ att_edge) {
    int wid = threadIdx.x >> 5, lane = threadIdx.x & 31;
    float s = 0.f;
    for (int c = lane; c < HD; c += 32)
        s += Wedge[wid * HD + c] * att_edge[wid * HD + c];
    #pragma unroll
    for (int o = 16; o; o >>= 1) s += __shfl_down_sync(0xffffffffu, s, o);
    if (lane == 0) g_scal[1 + wid] = s;
}

// ---------------- CSR build ----------------
__global__ void k_count(const int* __restrict__ ei, int E) {
    int e = blockIdx.x * blockDim.x + threadIdx.x;
    if (e < E) atomicAdd(&g_deg[ei[E + e]], 1);
}

__global__ __launch_bounds__(1024)
void k_scan(int N) {
    __shared__ int sh[1024];
    int t = threadIdx.x;
    int chunk = (N + 1023) / 1024;
    int s0 = min(t * chunk, N), s1 = min(s0 + chunk, N);
    int sum = 0;
    for (int n = s0; n < s1; n++) sum += g_deg[n] + 1;
    sh[t] = sum; __syncthreads();
    for (int o = 1; o < 1024; o <<= 1) {
        int v = (t >= o) ? sh[t - o] : 0;
        __syncthreads();
        sh[t] += v;
        __syncthreads();
    }
    int run = (t == 0) ? 0 : sh[t - 1];
    for (int n = s0; n < s1; n++) {
        g_off[n] = run;
        g_cur[n] = run;
        run += g_deg[n] + 1;
    }
    if (t == 1023) g_off[N] = sh[1023];
}

__global__ void k_fill(const int* __restrict__ ei, int E, int N) {
    int t = blockIdx.x * blockDim.x + threadIdx.x;
    if (t >= E + N) return;
    int d, s;
    if (t < E) { d = ei[E + t]; s = ei[t]; }
    else       { d = s = t - E; }
    int pos = atomicAdd(&g_cur[d], 1);
    g_csr[pos] = ((unsigned)t << 14) | (unsigned)s;
}

// ---------------- K4: fused alpha+exp (denom computed in agg) ----------------
__global__ void k_alphaexp(const int* __restrict__ ei, const float* __restrict__ ea,
                           int E, int N) {
    int t = blockIdx.x * blockDim.x + threadIdx.x;
    int total = (E + N) * HEADS;
    if (t >= total) return;
    int e = t >> 3, h = t & 7;
    int s, d; float av;
    if (e < E) { s = ei[e]; d = ei[E + e]; av = ea[e]; }
    else       { s = d = e - E;            av = g_scal[0] / (float)E; }
    float a = g_asrc[s * HEADS + h] + g_adst[d * HEADS + h] + av * g_scal[1 + h];
    a = (a >= 0.f) ? a : 0.2f * a;
    g_edge[t] = __expf(a);
}

// ---------------- K6: CSR agg (fp16 gathers) + in-warp denom + fused mean-pool ----------------
__global__ __launch_bounds__(256)
void k_agg(int N, const int* __restrict__ tip, const int* __restrict__ iip) {
    __shared__ float spool[OUTD];
    const int tid = threadIdx.x;
    for (int j = tid; j < OUTD; j += 256) spool[j] = 0.f;
    __syncthreads();

    int gw = (blockIdx.x * 256 + tid) >> 5;
    int lane = tid & 31;
    if (gw < N) {
        const int st = g_off[gw], en = g_off[gw + 1];
        const int hi4 = lane >> 4;

        float acc[4][8];
        float dsum[4];
        #pragma unroll
        for (int p = 0; p < 4; p++) {
            dsum[p] = 0.f;
            #pragma unroll
            for (int j = 0; j < 8; j++) acc[p][j] = 0.f;
        }

        #pragma unroll 2
        for (int i = st; i < en; i++) {
            unsigned pk = g_csr[i];
            int e = pk >> 14, s = pk & 0x3FFF;
            const uint4* rowq = (const uint4*)&g_xsh[(size_t)s * OUTD];
            const float* we = &g_edge[(size_t)e * HEADS];
            #pragma unroll
            for (int p = 0; p < 4; p++) {
                float w = we[p * 2 + hi4];
                uint4 v = rowq[p * 32 + lane];
                const __half2* hv = (const __half2*)&v;
                dsum[p] += w;
                #pragma unroll
                for (int q = 0; q < 4; q++) {
                    float2 f = __half22float2(hv[q]);
                    acc[p][q * 2]     += w * f.x;
                    acc[p][q * 2 + 1] += w * f.y;
                }
            }
        }
        #pragma unroll
        for (int p = 0; p < 4; p++) {
            float inv = 1.f / dsum[p];
            #pragma unroll
            for (int j = 0; j < 8; j++) acc[p][j] *= inv;
        }

        #pragma unroll
        for (int p = 0; p < 4; p++)
            #pragma unroll
            for (int jj = 0; jj < 8; jj++) {
                int j = (jj + lane) & 7;
                atomicAdd(&spool[p * 256 + lane * 8 + j], acc[p][j]);
            }

        int t = tip[0], im = iip[0];
        if (gw == t || gw == im) {
            float* out = &g_h[(size_t)gw * OUTD];
            #pragma unroll
            for (int p = 0; p < 4; p++) {
                *(float4*)&out[p * 256 + lane * 8]     = *(float4*)&acc[p][0];
                *(float4*)&out[p * 256 + lane * 8 + 4] = *(float4*)&acc[p][4];
            }
        }
    }
    __syncthreads();
    for (int j = tid; j < OUTD; j += 256) atomicAdd(&g_pool[j], spool[j]);
}

// ---------------- K8: fused vector + classifier ----------------
__global__ void k_clf(const float* __restrict__ bias,
                      const int* __restrict__ tip, const int* __restrict__ iip,
                      const float* __restrict__ clfW, const float* __restrict__ clfb,
                      int N, float* __restrict__ out) {
    __shared__ float s0[256], s1[256];
    int t = threadIdx.x;
    int ti = tip[0], im = iip[0];
    float a0 = 0.f, a1 = 0.f;
    for (int j = t; j < 3 * OUTD; j += 256) {
        int jj = j & (OUTD - 1);
        int seg = j >> 10;
        float b = bias[jj];
        float f;
        if (seg == 0)      f = g_pool[jj] / (float)N + b;
        else if (seg == 1) f = g_h[(size_t)ti * OUTD + jj] + b;
        else               f = g_h[(size_t)im * OUTD + jj] + b;
        a0 += f * clfW[2 * j];
        a1 += f * clfW[2 * j + 1];
    }
    s0[t] = a0; s1[t] = a1; __syncthreads();
    for (int o = 128; o; o >>= 1) {
        if (t < o) { s0[t] += s0[t + o]; s1[t] += s1[t + o]; }
        __syncthreads();
    }
    if (t == 0) {
        out[0] = s0[0] + clfb[0];
        out[1] = s1[0] + clfb[1];
    }
}

// ---------------- launch ----------------
extern "C" void kernel_launch(void* const* d_in, const int* in_sizes, int n_in,
                              void* d_out, int out_size) {
    const float* x        = (const float*)d_in[0];
    const int*   ei       = (const int*)  d_in[1];
    const float* ea       = (const float*)d_in[2];
    const int*   tip      = (const int*)  d_in[3];
    const int*   iip      = (const int*)  d_in[4];
    const float* W        = (const float*)d_in[5];
    const float* att_src  = (const float*)d_in[6];
    const float* att_dst  = (const float*)d_in[7];
    const float* Wedge    = (const float*)d_in[8];
    const float* att_edge = (const float*)d_in[9];
    const float* bias     = (const float*)d_in[10];
    const float* clfW     = (const float*)d_in[11];
    const float* clfb     = (const float*)d_in[12];
    float* out = (float*)d_out;

    int N  = in_sizes[0] / EMBED;
    int E  = in_sizes[1] / 2;
    int ET = E + N;

    static cudaStream_t s1, s2;
    static cudaEvent_t evFork, evCSR, evW;
    static int inited = 0;
    if (!inited) {
        cudaStreamCreateWithFlags(&s1, cudaStreamNonBlocking);
        cudaStreamCreateWithFlags(&s2, cudaStreamNonBlocking);
        cudaEventCreateWithFlags(&evFork, cudaEventDisableTiming);
        cudaEventCreateWithFlags(&evCSR,  cudaEventDisableTiming);
        cudaEventCreateWithFlags(&evW,    cudaEventDisableTiming);
        cudaFuncSetAttribute(k_gemm_mma, cudaFuncAttributeMaxDynamicSharedMemorySize, SMEM_GEMM);
        inited = 1;
    }

    void *p_pool, *p_deg, *p_scal;
    cudaGetSymbolAddress(&p_pool,  g_pool);
    cudaGetSymbolAddress(&p_deg,   g_deg);
    cudaGetSymbolAddress(&p_scal,  g_scal);

    // fork
    cudaEventRecord(evFork, 0);
    cudaStreamWaitEvent(s1, evFork, 0);
    cudaStreamWaitEvent(s2, evFork, 0);

    // s1: CSR build + scalar reductions + small memsets
    cudaMemsetAsync(p_pool, 0, OUTD * sizeof(float), s1);
    cudaMemsetAsync(p_deg,  0, (size_t)N * sizeof(int), s1);
    cudaMemsetAsync(p_scal, 0, sizeof(float), s1);
    k_count<<<(E + 255) / 256, 256, 0, s1>>>(ei, E);
    k_scan<<<1, 1024, 0, s1>>>(N);
    k_fill<<<(ET + 255) / 256, 256, 0, s1>>>(ei, E, N);
    k_easum<<<64, 256, 0, s1>>>(ea, E);
    k_kcoef<<<1, 256, 0, s1>>>(Wedge, att_edge);
    cudaEventRecord(evCSR, s1);

    // s2: weight conversion (coalesced transpose, fp16)
    {
        dim3 gw2(OUTD / 32, EMBED / 32);
        k_cvtW<<<gw2, 256, 0, s2>>>(W);
    }
    cudaEventRecord(evW, s2);

    // main: GEMM (fp16 2-term, in-kernel A conversion, fused logits) -> alphaexp -> agg -> clf
    cudaStreamWaitEvent(0, evW, 0);
    dim3 gg(OUTD / 128, PADN / 128);
    k_gemm_mma<<<gg, 256, SMEM_GEMM>>>(N, x, att_src, att_dst);

    cudaStreamWaitEvent(0, evCSR, 0);
    int totalEH = ET * HEADS;
    k_alphaexp<<<(totalEH + 255) / 256, 256>>>(ei, ea, E, N);
    k_agg<<<(N * 32 + 255) / 256, 256>>>(N, tip, iip);

    k_clf<<<1, 256>>>(bias, tip, iip, clfW, clfb, N, out);
}

// round 14
// speedup vs baseline: 1.5468x; 1.2193x over previous
#include <cuda_runtime.h>
#include <cuda_fp16.h>
#include <cstdint>

#define EMBED 768
#define OUTD  1024
#define HEADS 8
#define HD    128
#define MAXN  10000
#define MAXE  160000
#define MAXET (MAXN + MAXE)
#define PADN  10112            // 79 * 128

// ---------------- scratch ----------------
__device__ __half   g_xsh[(size_t)MAXN * OUTD];   // fp16 xs for aggregation (20 MB)
__device__ float    g_h[MAXN * OUTD];             // only rows text/image are written
__device__ float    g_asrc[MAXN * HEADS];
__device__ float    g_adst[MAXN * HEADS];
__device__ float    g_edge[MAXET * HEADS];
__device__ float    g_scal[16];                   // [0]=sum(ea), [1..8]=k[h]
__device__ float    g_pool[OUTD];
// CSR by dst
__device__ int      g_deg[MAXN];
__device__ int      g_off[MAXN + 1];
__device__ int      g_cur[MAXN];
__device__ unsigned g_csr[MAXET];                 // (edge_id << 14) | src
// fp16 W^T for tensor-core GEMM
__device__ __half   g_Wh[(size_t)OUTD * EMBED];   // W^T [n][k], fp16

// ---------------- PTX helpers ----------------
__device__ __forceinline__ uint32_t smem_u32(const void* p) {
    uint32_t a;
    asm("{ .reg .u64 t; cvta.to.shared.u64 t, %1; cvt.u32.u64 %0, t; }" : "=r"(a) : "l"(p));
    return a;
}
__device__ __forceinline__ void cp16(uint32_t s, const void* g) {
    asm volatile("cp.async.cg.shared.global [%0], [%1], 16;" :: "r"(s), "l"(g));
}
__device__ __forceinline__ void cp_commit() {
    asm volatile("cp.async.commit_group;" ::: "memory");
}
template <int N>
__device__ __forceinline__ void cp_wait() {
    asm volatile("cp.async.wait_group %0;" :: "n"(N) : "memory");
}
__device__ __forceinline__ void ldsm4(uint32_t& r0, uint32_t& r1, uint32_t& r2, uint32_t& r3,
                                      uint32_t addr) {
    asm volatile("ldmatrix.sync.aligned.m8n8.x4.shared.b16 {%0,%1,%2,%3}, [%4];"
                 : "=r"(r0), "=r"(r1), "=r"(r2), "=r"(r3) : "r"(addr));
}
__device__ __forceinline__ void mma16816h(float* d, const uint32_t* a, const uint32_t* b) {
    asm volatile(
        "mma.sync.aligned.m16n8k16.row.col.f32.f16.f16.f32 "
        "{%0,%1,%2,%3}, {%4,%5,%6,%7}, {%8,%9}, {%0,%1,%2,%3};"
        : "+f"(d[0]), "+f"(d[1]), "+f"(d[2]), "+f"(d[3])
        : "r"(a[0]), "r"(a[1]), "r"(a[2]), "r"(a[3]), "r"(b[0]), "r"(b[1]));
}

__device__ __forceinline__ uint32_t sw_off(int row, int c) {
    return (uint32_t)(row * 64 + ((c ^ ((row >> 1) & 3)) << 4));
}

// ---------------- K0b: W^T fp16 via smem tile transpose ----------------
__global__ __launch_bounds__(256)
void k_cvtW(const float* __restrict__ W) {
    __shared__ float tile[32][33];
    const int k0 = blockIdx.y * 32;
    const int n0 = blockIdx.x * 32;
    const int tx = threadIdx.x & 31, ty = threadIdx.x >> 5;
    #pragma unroll
    for (int i = 0; i < 32; i += 8)
        tile[ty + i][tx] = W[(size_t)(k0 + ty + i) * OUTD + n0 + tx];
    __syncthreads();
    #pragma unroll
    for (int i = 0; i < 32; i += 8)
        g_Wh[(size_t)(n0 + ty + i) * EMBED + k0 + tx] = __float2half(tile[tx][ty + i]);
}

// ---------------- K2: HMMA fp16 GEMM, in-kernel A conversion, fused logits ----------------
#define KCH    32
#define NCHUNK (EMBED / KCH)      // 24
#define TILEB  (128 * 64)         // 8 KB
#define STAGEB (2 * TILEB)        // A, B = 16 KB
#define NSTAGE 3
#define SMEM_GEMM (NSTAGE * STAGEB)

__global__ __launch_bounds__(256, 2)
void k_gemm_mma(int M, const float* __restrict__ x,
                const float* __restrict__ att_src,
                const float* __restrict__ att_dst) {
    extern __shared__ char smem[];
    const uint32_t sb = smem_u32(smem);
    const int tid = threadIdx.x;
    const int wid = tid >> 5, lane = tid & 31;
    const int warp_m = wid & 3;
    const int warp_n = wid >> 2;
    const int rowBase = blockIdx.y * 128;
    const int colBase = blockIdx.x * 128;
    const int head = colBase >> 7;

    const __half* srcB = g_Wh + (size_t)colBase * EMBED;

    const int chunk0 = tid * 2;
    const int row0 = chunk0 >> 2, cc0 = chunk0 & 3;
    const int row1 = (chunk0 + 1) >> 2, cc1 = (chunk0 + 1) & 3;
    const uint32_t so0 = sw_off(row0, cc0);
    const uint32_t so1 = sw_off(row1, cc1);
    const int rowg0 = rowBase + row0, rowg1 = rowBase + row1;
    const float4* xv = (const float4*)x;

    float af[16];

    auto ldA = [&](int c) {
        int kb = c * 8;
        if (rowg0 < M) {
            *(float4*)&af[0] = xv[(size_t)rowg0 * (EMBED / 4) + kb + cc0 * 2];
            *(float4*)&af[4] = xv[(size_t)rowg0 * (EMBED / 4) + kb + cc0 * 2 + 1];
        } else {
            #pragma unroll
            for (int j = 0; j < 8; j++) af[j] = 0.f;
        }
        if (rowg1 < M) {
            *(float4*)&af[8]  = xv[(size_t)rowg1 * (EMBED / 4) + kb + cc1 * 2];
            *(float4*)&af[12] = xv[(size_t)rowg1 * (EMBED / 4) + kb + cc1 * 2 + 1];
        } else {
            #pragma unroll
            for (int j = 8; j < 16; j++) af[j] = 0.f;
        }
    };

    auto stsA = [&](int s) {
        const uint32_t stOff = (uint32_t)(s * STAGEB);
        #pragma unroll
        for (int ch = 0; ch < 2; ch++) {
            const float* f = &af[ch * 8];
            __half2 H[4];
            #pragma unroll
            for (int j = 0; j < 4; j++)
                H[j] = __floats2half2_rn(f[2 * j], f[2 * j + 1]);
            uint32_t off = (ch == 0) ? so0 : so1;
            *(uint4*)(smem + stOff + off) = *(uint4*)H;
        }
    };

    auto cpB = [&](int c, int s) {
        const uint32_t base = sb + s * STAGEB;
        const int k0 = c * KCH;
        cp16(base + TILEB + so0, srcB + (size_t)row0 * EMBED + k0 + cc0 * 8);
        cp16(base + TILEB + so1, srcB + (size_t)row1 * EMBED + k0 + cc1 * 8);
        cp_commit();
    };

    ldA(0);
    cpB(0, 0);
    cpB(1, 1);

    float acc[2][8][4];
    #pragma unroll
    for (int mb = 0; mb < 2; mb++)
        #pragma unroll
        for (int nb = 0; nb < 8; nb++)
            #pragma unroll
            for (int j = 0; j < 4; j++) acc[mb][nb][j] = 0.f;

    const int l_tile = lane >> 3, l_rin = lane & 7;

    for (int c = 0; c < NCHUNK; c++) {
        const int s = c % NSTAGE;
        stsA(s);
        if (c + 1 < NCHUNK) cp_wait<1>(); else cp_wait<0>();
        __syncthreads();
        if (c + 1 < NCHUNK) ldA(c + 1);
        if (c + 2 < NCHUNK) cpB(c + 2, (c + 2) % NSTAGE);

        const uint32_t base = sb + s * STAGEB;
        #pragma unroll
        for (int ks = 0; ks < 2; ks++) {
            uint32_t a[2][4];
            uint32_t b[8][2];
            #pragma unroll
            for (int mb = 0; mb < 2; mb++) {
                int r = warp_m * 32 + mb * 16 + ((l_tile & 1) << 3) + l_rin;
                int cch = ks * 2 + (l_tile >> 1);
                ldsm4(a[mb][0], a[mb][1], a[mb][2], a[mb][3],
                      base + sw_off(r, cch));
            }
            #pragma unroll
            for (int p = 0; p < 4; p++) {
                int r = warp_n * 64 + p * 16 + ((l_tile >> 1) << 3) + l_rin;
                int cch = ks * 2 + (l_tile & 1);
                ldsm4(b[p * 2][0], b[p * 2][1],
                      b[p * 2 + 1][0], b[p * 2 + 1][1],
                      base + TILEB + sw_off(r, cch));
            }
            #pragma unroll
            for (int mb = 0; mb < 2; mb++)
                #pragma unroll
                for (int nb = 0; nb < 8; nb++)
                    mma16816h(acc[mb][nb], a[mb], b[nb]);
        }
    }

    // ---- epilogue: logits via smem + fp16 xs store ----
    __syncthreads();
    float* sasrc = (float*)smem;
    float* sadst = sasrc + 128;
    ((float*)smem)[tid] = 0.f;
    __syncthreads();

    const int tr = lane >> 2, tc = (lane & 3) * 2;

    float as[16], ad[16];
    #pragma unroll
    for (int nb = 0; nb < 8; nb++)
        #pragma unroll
        for (int j = 0; j < 2; j++) {
            int col = warp_n * 64 + nb * 8 + tc + j;
            as[nb * 2 + j] = att_src[head * HD + col];
            ad[nb * 2 + j] = att_dst[head * HD + col];
        }

    #pragma unroll
    for (int mb = 0; mb < 2; mb++) {
        #pragma unroll
        for (int half = 0; half < 2; half++) {
            int rloc = warp_m * 32 + mb * 16 + half * 8 + tr;
            int row = rowBase + rloc;
            float ps = 0.f, pd = 0.f;
            #pragma unroll
            for (int nb = 0; nb < 8; nb++)
                #pragma unroll
                for (int j = 0; j < 2; j++) {
                    float v = acc[mb][nb][half * 2 + j];
                    ps += v * as[nb * 2 + j];
                    pd += v * ad[nb * 2 + j];
                }
            #pragma unroll
            for (int o = 1; o < 4; o <<= 1) {
                ps += __shfl_xor_sync(0xffffffffu, ps, o);
                pd += __shfl_xor_sync(0xffffffffu, pd, o);
            }
            if (row < M) {
                if ((lane & 3) == 0) {
                    atomicAdd(&sasrc[rloc], ps);
                    atomicAdd(&sadst[rloc], pd);
                }
                __half* dst = &g_xsh[(size_t)row * OUTD + colBase + warp_n * 64 + tc];
                #pragma unroll
                for (int nb = 0; nb < 8; nb++) {
                    __half2 v = __floats2half2_rn(acc[mb][nb][half * 2],
                                                  acc[mb][nb][half * 2 + 1]);
                    *(__half2*)(dst + nb * 8) = v;
                }
            }
        }
    }
    __syncthreads();
    if (tid < 128) {
        int row = rowBase + tid;
        if (row < M) {
            g_asrc[row * HEADS + head] = sasrc[tid];
            g_adst[row * HEADS + head] = sadst[tid];
        }
    }
}

// ---------------- K1a: parallel sum of ea ----------------
__global__ void k_easum(const float* __restrict__ ea, int E) {
    __shared__ float sh[256];
    float s = 0.f;
    for (int i = blockIdx.x * 256 + threadIdx.x; i < E; i += gridDim.x * 256) s += ea[i];
    sh[threadIdx.x] = s; __syncthreads();
    for (int o = 128; o; o >>= 1) {
        if (threadIdx.x < o) sh[threadIdx.x] += sh[threadIdx.x + o];
        __syncthreads();
    }
    if (threadIdx.x == 0) atomicAdd(&g_scal[0], sh[0]);
}

// ---------------- K1b: per-head edge coefficient k[h] ----------------
__global__ void k_kcoef(const float* __restrict__ Wedge,
                        const float* __restrict__ att_edge) {
    int wid = threadIdx.x >> 5, lane = threadIdx.x & 31;
    float s = 0.f;
    for (int c = lane; c < HD; c += 32)
        s += Wedge[wid * HD + c] * att_edge[wid * HD + c];
    #pragma unroll
    for (int o = 16; o; o >>= 1) s += __shfl_down_sync(0xffffffffu, s, o);
    if (lane == 0) g_scal[1 + wid] = s;
}

// ---------------- CSR build ----------------
__global__ void k_count(const int* __restrict__ ei, int E) {
    int e = blockIdx.x * blockDim.x + threadIdx.x;
    if (e < E) atomicAdd(&g_deg[ei[E + e]], 1);
}

__global__ __launch_bounds__(1024)
void k_scan(int N) {
    __shared__ int sh[1024];
    int t = threadIdx.x;
    int chunk = (N + 1023) / 1024;
    int s0 = min(t * chunk, N), s1 = min(s0 + chunk, N);
    int sum = 0;
    for (int n = s0; n < s1; n++) sum += g_deg[n] + 1;
    sh[t] = sum; __syncthreads();
    for (int o = 1; o < 1024; o <<= 1) {
        int v = (t >= o) ? sh[t - o] : 0;
        __syncthreads();
        sh[t] += v;
        __syncthreads();
    }
    int run = (t == 0) ? 0 : sh[t - 1];
    for (int n = s0; n < s1; n++) {
        g_off[n] = run;
        g_cur[n] = run;
        run += g_deg[n] + 1;
    }
    if (t == 1023) g_off[N] = sh[1023];
}

__global__ void k_fill(const int* __restrict__ ei, int E, int N) {
    int t = blockIdx.x * blockDim.x + threadIdx.x;
    if (t >= E + N) return;
    int d, s;
    if (t < E) { d = ei[E + t]; s = ei[t]; }
    else       { d = s = t - E; }
    int pos = atomicAdd(&g_cur[d], 1);
    g_csr[pos] = ((unsigned)t << 14) | (unsigned)s;
}

// ---------------- K4: fused alpha+exp (denom computed in agg) ----------------
__global__ void k_alphaexp(const int* __restrict__ ei, const float* __restrict__ ea,
                           int E, int N) {
    int t = blockIdx.x * blockDim.x + threadIdx.x;
    int total = (E + N) * HEADS;
    if (t >= total) return;
    int e = t >> 3, h = t & 7;
    int s, d; float av;
    if (e < E) { s = ei[e]; d = ei[E + e]; av = ea[e]; }
    else       { s = d = e - E;            av = g_scal[0] / (float)E; }
    float a = g_asrc[s * HEADS + h] + g_adst[d * HEADS + h] + av * g_scal[1 + h];
    a = (a >= 0.f) ? a : 0.2f * a;
    g_edge[t] = __expf(a);
}

// ---------------- K6: CSR agg (fp16 gathers) + in-warp denom + fused mean-pool ----------------
__global__ __launch_bounds__(256)
void k_agg(int N, const int* __restrict__ tip, const int* __restrict__ iip) {
    __shared__ float spool[OUTD];
    const int tid = threadIdx.x;
    for (int j = tid; j < OUTD; j += 256) spool[j] = 0.f;
    __syncthreads();

    int gw = (blockIdx.x * 256 + tid) >> 5;
    int lane = tid & 31;
    if (gw < N) {
        const int st = g_off[gw], en = g_off[gw + 1];
        const int hi4 = lane >> 4;

        float acc[4][8];
        float dsum[4];
        #pragma unroll
        for (int p = 0; p < 4; p++) {
            dsum[p] = 0.f;
            #pragma unroll
            for (int j = 0; j < 8; j++) acc[p][j] = 0.f;
        }

        #pragma unroll 2
        for (int i = st; i < en; i++) {
            unsigned pk = g_csr[i];
            int e = pk >> 14, s = pk & 0x3FFF;
            const uint4* rowq = (const uint4*)&g_xsh[(size_t)s * OUTD];
            const float* we = &g_edge[(size_t)e * HEADS];
            #pragma unroll
            for (int p = 0; p < 4; p++) {
                float w = we[p * 2 + hi4];
                uint4 v = rowq[p * 32 + lane];
                const __half2* hv = (const __half2*)&v;
                dsum[p] += w;
                #pragma unroll
                for (int q = 0; q < 4; q++) {
                    float2 f = __half22float2(hv[q]);
                    acc[p][q * 2]     += w * f.x;
                    acc[p][q * 2 + 1] += w * f.y;
                }
            }
        }
        #pragma unroll
        for (int p = 0; p < 4; p++) {
            float inv = 1.f / dsum[p];
            #pragma unroll
            for (int j = 0; j < 8; j++) acc[p][j] *= inv;
        }

        #pragma unroll
        for (int p = 0; p < 4; p++)
            #pragma unroll
            for (int jj = 0; jj < 8; jj++) {
                int j = (jj + lane) & 7;
                atomicAdd(&spool[p * 256 + lane * 8 + j], acc[p][j]);
            }

        int t = tip[0], im = iip[0];
        if (gw == t || gw == im) {
            float* out = &g_h[(size_t)gw * OUTD];
            #pragma unroll
            for (int p = 0; p < 4; p++) {
                *(float4*)&out[p * 256 + lane * 8]     = *(float4*)&acc[p][0];
                *(float4*)&out[p * 256 + lane * 8 + 4] = *(float4*)&acc[p][4];
            }
        }
    }
    __syncthreads();
    for (int j = tid; j < OUTD; j += 256) atomicAdd(&g_pool[j], spool[j]);
}

// ---------------- K8: fused vector + classifier ----------------
__global__ void k_clf(const float* __restrict__ bias,
                      const int* __restrict__ tip, const int* __restrict__ iip,
                      const float* __restrict__ clfW, const float* __restrict__ clfb,
                      int N, float* __restrict__ out) {
    __shared__ float s0[256], s1[256];
    int t = threadIdx.x;
    int ti = tip[0], im = iip[0];
    float a0 = 0.f, a1 = 0.f;
    for (int j = t; j < 3 * OUTD; j += 256) {
        int jj = j & (OUTD - 1);
        int seg = j >> 10;
        float b = bias[jj];
        float f;
        if (seg == 0)      f = g_pool[jj] / (float)N + b;
        else if (seg == 1) f = g_h[(size_t)ti * OUTD + jj] + b;
        else               f = g_h[(size_t)im * OUTD + jj] + b;
        a0 += f * clfW[2 * j];
        a1 += f * clfW[2 * j + 1];
    }
    s0[t] = a0; s1[t] = a1; __syncthreads();
    for (int o = 128; o; o >>= 1) {
        if (t < o) { s0[t] += s0[t + o]; s1[t] += s1[t + o]; }
        __syncthreads();
    }
    if (t == 0) {
        out[0] = s0[0] + clfb[0];
        out[1] = s1[0] + clfb[1];
    }
}

// ---------------- launch ----------------
extern "C" void kernel_launch(void* const* d_in, const int* in_sizes, int n_in,
                              void* d_out, int out_size) {
    const float* x        = (const float*)d_in[0];
    const int*   ei       = (const int*)  d_in[1];
    const float* ea       = (const float*)d_in[2];
    const int*   tip      = (const int*)  d_in[3];
    const int*   iip      = (const int*)  d_in[4];
    const float* W        = (const float*)d_in[5];
    const float* att_src  = (const float*)d_in[6];
    const float* att_dst  = (const float*)d_in[7];
    const float* Wedge    = (const float*)d_in[8];
    const float* att_edge = (const float*)d_in[9];
    const float* bias     = (const float*)d_in[10];
    const float* clfW     = (const float*)d_in[11];
    const float* clfb     = (const float*)d_in[12];
    float* out = (float*)d_out;

    int N  = in_sizes[0] / EMBED;
    int E  = in_sizes[1] / 2;
    int ET = E + N;

    static cudaStream_t s1, s2;
    static cudaEvent_t evFork, evCSR, evW;
    static int inited = 0;
    if (!inited) {
        cudaStreamCreateWithFlags(&s1, cudaStreamNonBlocking);
        cudaStreamCreateWithFlags(&s2, cudaStreamNonBlocking);
        cudaEventCreateWithFlags(&evFork, cudaEventDisableTiming);
        cudaEventCreateWithFlags(&evCSR,  cudaEventDisableTiming);
        cudaEventCreateWithFlags(&evW,    cudaEventDisableTiming);
        cudaFuncSetAttribute(k_gemm_mma, cudaFuncAttributeMaxDynamicSharedMemorySize, SMEM_GEMM);
        inited = 1;
    }

    void *p_pool, *p_deg, *p_scal;
    cudaGetSymbolAddress(&p_pool,  g_pool);
    cudaGetSymbolAddress(&p_deg,   g_deg);
    cudaGetSymbolAddress(&p_scal,  g_scal);

    // fork
    cudaEventRecord(evFork, 0);
    cudaStreamWaitEvent(s1, evFork, 0);
    cudaStreamWaitEvent(s2, evFork, 0);

    // s1: CSR build + scalar reductions + small memsets
    cudaMemsetAsync(p_pool, 0, OUTD * sizeof(float), s1);
    cudaMemsetAsync(p_deg,  0, (size_t)N * sizeof(int), s1);
    cudaMemsetAsync(p_scal, 0, sizeof(float), s1);
    k_count<<<(E + 255) / 256, 256, 0, s1>>>(ei, E);
    k_scan<<<1, 1024, 0, s1>>>(N);
    k_fill<<<(ET + 255) / 256, 256, 0, s1>>>(ei, E, N);
    k_easum<<<64, 256, 0, s1>>>(ea, E);
    k_kcoef<<<1, 256, 0, s1>>>(Wedge, att_edge);
    cudaEventRecord(evCSR, s1);

    // s2: weight conversion (coalesced transpose, fp16)
    {
        dim3 gw2(OUTD / 32, EMBED / 32);
        k_cvtW<<<gw2, 256, 0, s2>>>(W);
    }
    cudaEventRecord(evW, s2);

    // main: GEMM (fp16, in-kernel A conversion, fused logits) -> alphaexp -> agg -> clf
    cudaStreamWaitEvent(0, evW, 0);
    dim3 gg(OUTD / 128, PADN / 128);
    k_gemm_mma<<<gg, 256, SMEM_GEMM>>>(N, x, att_src, att_dst);

    cudaStreamWaitEvent(0, evCSR, 0);
    int totalEH = ET * HEADS;
    k_alphaexp<<<(totalEH + 255) / 256, 256>>>(ei, ea, E, N);
    k_agg<<<(N * 32 + 255) / 256, 256>>>(N, tip, iip);

    k_clf<<<1, 256>>>(bias, tip, iip, clfW, clfb, N, out);
}